// round 13
// baseline (speedup 1.0000x reference)
#include <cuda_runtime.h>
#include <cuda_fp16.h>
#include <cstdint>
#include <cstddef>

namespace {
constexpr int kT = 8192, kD = 2048, kF = 4096, kE = 8;
constexpr int TMm = 128;
constexpr int TN  = 128;
constexpr int ROWT = kT / TMm + kE;
constexpr int TPAD = ROWT * TMm;
constexpr int BK = 64;
constexpr int ST = 3;
constexpr int A_BYTES = TMm * BK * 2;
constexpr int B_BYTES = TN * BK * 2;
constexpr int STG = A_BYTES + B_BYTES;
constexpr int SMEM_BYTES = ST * STG;     // 96 KB -> 2 CTAs/SM
constexpr int NTH = 128;

constexpr int XT1 = kF / TN;             // 32
constexpr int XT2 = kD / TN;             // 16
constexpr int NT1 = XT1 * ROWT;          // 2304
constexpr int NT2 = XT2 * ROWT;          // 1152
constexpr int NXP = ROWT;                // 72
constexpr int NW1 = kE * XT1;            // 256
constexpr int NW2 = kE * XT2;            // 128
constexpr int PREP = NXP + NW1;          // 328
constexpr int MIXLEN = 4 * NW2;          // 512
constexpr int G1END = PREP + NT1 + NW2;  // 2760
constexpr int TOTAL = G1END + NT2;       // 3912
constexpr int W1_UNIT_N8 = 128 * kD / 8;
constexpr int W2_UNIT_N8 = 128 * kF / 8;
}

__device__ int g_cursor[kE];
__device__ int g_rowtoken[TPAD];
__device__ int g_tile_expert[ROWT];
__device__ int g_xrdy[NXP];
__device__ int g_w1rdy[NW1];
__device__ int g_w2rdy[NW2];
__device__ int g_done1[ROWT];
__device__ __half g_xperm[(size_t)TPAD * kD];
__device__ __half g_w1h[(size_t)kE * kF * kD];
__device__ __half g_w2h[(size_t)kE * kD * kF];
__device__ __half g_h1h[(size_t)TPAD * kF];

__device__ __forceinline__ uint32_t smem_u32(const void* p) {
    uint32_t a;
    asm("{ .reg .u64 t; cvta.to.shared.u64 t, %1; cvt.u32.u64 %0, t; }" : "=r"(a) : "l"(p));
    return a;
}
__device__ __forceinline__ void ldsm_x4(uint32_t* r, uint32_t addr) {
    asm volatile("ldmatrix.sync.aligned.m8n8.x4.shared.b16 {%0,%1,%2,%3}, [%4];"
                 : "=r"(r[0]), "=r"(r[1]), "=r"(r[2]), "=r"(r[3]) : "r"(addr));
}
__device__ __forceinline__ void mma_f16(float* c, const uint32_t* a, uint32_t b0, uint32_t b1) {
    asm volatile(
        "mma.sync.aligned.m16n8k16.row.col.f32.f16.f16.f32 "
        "{%0,%1,%2,%3}, {%4,%5,%6,%7}, {%8,%9}, {%0,%1,%2,%3};\n"
        : "+f"(c[0]), "+f"(c[1]), "+f"(c[2]), "+f"(c[3])
        : "r"(a[0]), "r"(a[1]), "r"(a[2]), "r"(a[3]), "r"(b0), "r"(b1));
}
__device__ __forceinline__ void cp_async16(uint32_t dst, const void* src) {
    asm volatile("cp.async.cg.shared.global [%0], [%1], 16;" :: "r"(dst), "l"(src));
}
__device__ __forceinline__ void cvt8(const float4* __restrict__ s, uint4* __restrict__ d) {
    float4 a = s[0], b = s[1];
    __half2 h0 = __floats2half2_rn(a.x, a.y), h1 = __floats2half2_rn(a.z, a.w);
    __half2 h2 = __floats2half2_rn(b.x, b.y), h3 = __floats2half2_rn(b.z, b.w);
    uint4 o;
    o.x = *(uint32_t*)&h0; o.y = *(uint32_t*)&h1;
    o.z = *(uint32_t*)&h2; o.w = *(uint32_t*)&h3;
    *d = o;
}
__device__ __forceinline__ int ld_acquire(const int* p) {
    int v;
    asm volatile("ld.acquire.gpu.global.b32 %0, [%1];" : "=r"(v) : "l"(p) : "memory");
    return v;
}
__device__ __forceinline__ void publish(int* flag) {
    __threadfence();
    __syncthreads();
    if (threadIdx.x == 0) atomicExch(flag, 1);
}

__global__ void k_route(const float* __restrict__ logits) {
    int t = blockIdx.x * blockDim.x + threadIdx.x;
    if (t >= kT) return;
    const float* l = logits + (size_t)t * kE;
    int best = 0; float bv = l[0];
#pragma unroll
    for (int e = 1; e < kE; e++) { float v = l[e]; if (v > bv) { bv = v; best = e; } }
    ((int*)g_xperm)[t] = best;
}
__global__ void k_offsets() {
    __shared__ int sc[kE];
    if (threadIdx.x < kE) sc[threadIdx.x] = 0;
    __syncthreads();
    for (int t = threadIdx.x; t < kT; t += blockDim.x)
        atomicAdd(&sc[((int*)g_xperm)[t]], 1);
    __syncthreads();
    if (threadIdx.x == 0) {
        int off = 0;
        for (int e = 0; e < kE; e++) {
            g_cursor[e] = off;
            int nt = (sc[e] + TMm - 1) / TMm;
            for (int i = 0; i < nt; i++) g_tile_expert[off / TMm + i] = e;
            off += nt * TMm;
        }
        for (int rt = off / TMm; rt < ROWT; rt++) g_tile_expert[rt] = -1;
    }
    for (int i = threadIdx.x; i < TPAD; i += blockDim.x) g_rowtoken[i] = -1;
    for (int i = threadIdx.x; i < NXP; i += blockDim.x) { g_xrdy[i] = 0; g_done1[i] = 0; }
    for (int i = threadIdx.x; i < NW1; i += blockDim.x) g_w1rdy[i] = 0;
    for (int i = threadIdx.x; i < NW2; i += blockDim.x) g_w2rdy[i] = 0;
}
__global__ void k_scatter() {
    int t = blockIdx.x * blockDim.x + threadIdx.x;
    if (t >= kT) return;
    int e = ((int*)g_xperm)[t];
    int pos = atomicAdd(&g_cursor[e], 1);
    g_rowtoken[pos] = t;
}

template <bool FIRST>
__device__ __forceinline__ void gemm_tile(int rt, int e, int xblk, uint32_t sb,
                                          float* __restrict__ out)
{
    constexpr int K = FIRST ? kD : kF;
    constexpr int NC = K / BK;
    const int rowbase = rt * TMm;
    const int colbase = xblk * TN;

    const int tid = threadIdx.x;
    const int warp = tid >> 5, lane = tid & 31;
    const int wm = warp & 1, wn = warp >> 1;

    const __half* Abase = FIRST ? g_xperm : g_h1h;
    const __half* Wb = (FIRST ? g_w1h : g_w2h) + (size_t)e * ((size_t)(FIRST ? kF : kD) * K);

    const int q = tid & 7, r = tid >> 3;
    const __half* aptr = Abase + (size_t)(rowbase + r) * K + q * 8;
    const __half* bptr = Wb + (size_t)(colbase + r) * K + q * 8;
    const uint32_t dA = (uint32_t)(r * 128 + ((q ^ (r & 7)) << 4));

    auto prefetch = [&](int c) {
        const uint32_t base = sb + (uint32_t)((c % ST) * STG);
        const __half* ap = aptr + c * BK;
#pragma unroll
        for (int p = 0; p < 8; p++)
            cp_async16(base + dA + (uint32_t)(p * 16 * 128), ap + (size_t)p * 16 * K);
        const __half* bp = bptr + c * BK;
#pragma unroll
        for (int p = 0; p < 8; p++)
            cp_async16(base + A_BYTES + dA + (uint32_t)(p * 16 * 128), bp + (size_t)p * 16 * K);
        asm volatile("cp.async.commit_group;" ::: "memory");
    };

    prefetch(0);
    prefetch(1);

    const int rowA = wm * 64 + (lane & 15);
    const int kgA = lane >> 4;
    const int rowB = wn * 64 + ((lane >> 4) << 3) + (lane & 7);
    const int kgB = (lane >> 3) & 1;

    float acc[4][8][4];
#pragma unroll
    for (int i = 0; i < 4; i++)
#pragma unroll
        for (int j = 0; j < 8; j++)
#pragma unroll
            for (int v = 0; v < 4; v++) acc[i][j][v] = 0.f;

#pragma unroll 1
    for (int c = 0; c < NC; c++) {
        if (c < NC - 1) asm volatile("cp.async.wait_group 1;" ::: "memory");
        else            asm volatile("cp.async.wait_group 0;" ::: "memory");
        __syncthreads();
        if (c + 2 < NC) prefetch(c + 2);

        const uint32_t stA = sb + (uint32_t)((c % ST) * STG);
        const uint32_t stB = stA + A_BYTES;
#pragma unroll
        for (int s = 0; s < 4; s++) {
            uint32_t a[4][4];
#pragma unroll
            for (int mi = 0; mi < 4; mi++) {
                const int rr = rowA + mi * 16;
                ldsm_x4(a[mi], stA + (uint32_t)(rr * 128 + (((2 * s + kgA) ^ (rr & 7)) << 4)));
            }
            uint32_t b[4][4];
#pragma unroll
            for (int nj2 = 0; nj2 < 4; nj2++) {
                const int rr = rowB + nj2 * 16;
                ldsm_x4(b[nj2], stB + (uint32_t)(rr * 128 + (((2 * s + kgB) ^ (rr & 7)) << 4)));
            }
#pragma unroll
            for (int mi = 0; mi < 4; mi++)
#pragma unroll
                for (int nj = 0; nj < 8; nj++)
                    mma_f16(acc[mi][nj], a[mi], b[nj >> 1][(nj & 1) * 2], b[nj >> 1][(nj & 1) * 2 + 1]);
        }
    }

    const int g = lane >> 2, tig = lane & 3;
#pragma unroll
    for (int mi = 0; mi < 4; mi++) {
#pragma unroll
        for (int rr = 0; rr < 2; rr++) {
            const int lrow = rowbase + wm * 64 + mi * 16 + g + rr * 8;
            if (FIRST) {
                __half* hp = g_h1h + (size_t)lrow * kF + colbase;
#pragma unroll
                for (int nj = 0; nj < 8; nj++) {
                    const int col = wn * 64 + nj * 8 + tig * 2;
                    float v0 = acc[mi][nj][rr * 2 + 0];
                    float v1 = acc[mi][nj][rr * 2 + 1];
                    v0 = v0 / (1.f + __expf(-v0));
                    v1 = v1 / (1.f + __expf(-v1));
                    __half2 h = __floats2half2_rn(v0, v1);
                    *(uint32_t*)(hp + col) = *(uint32_t*)&h;
                }
            } else {
                const int tok = g_rowtoken[lrow];
                if (tok >= 0) {
                    float* op = out + (size_t)tok * kD + colbase;
#pragma unroll
                    for (int nj = 0; nj < 8; nj++) {
                        const int col = wn * 64 + nj * 8 + tig * 2;
                        float2 st;
                        st.x = acc[mi][nj][rr * 2 + 0];
                        st.y = acc[mi][nj][rr * 2 + 1];
                        *(float2*)(op + col) = st;
                    }
                }
            }
        }
    }
}

__global__ __launch_bounds__(NTH, 2) void k_moe(const float4* __restrict__ w1src,
                                                const float4* __restrict__ w2src,
                                                const float4* __restrict__ hs,
                                                float* __restrict__ out)
{
    extern __shared__ char smem[];
    const uint32_t sb = smem_u32(smem);
    const int tid = threadIdx.x;
    const int id = blockIdx.x;

    if (id < NXP) {
        const int rt = id;
#pragma unroll 4
        for (int i = tid; i < 128 * 256; i += NTH) {
            const int row = rt * 128 + (i >> 8);
            const int q = i & 255;
            const int tok = g_rowtoken[row];
            uint4 o = make_uint4(0, 0, 0, 0);
            if (tok >= 0) cvt8(hs + (size_t)tok * (kD / 4) + 2 * q, &o);
            ((uint4*)g_xperm)[(size_t)row * 256 + q] = o;
        }
        publish(&g_xrdy[rt]);
        return;
    }
    if (id < PREP) {
        const int u = id - NXP;
        const long long base8 = ((long long)(u >> 5) * kF + (long long)(u & 31) * 128) * kD / 8;
        uint4* dst = (uint4*)g_w1h + base8;
        const float4* src = w1src + 2 * base8;
#pragma unroll 4
        for (int i = tid; i < W1_UNIT_N8; i += NTH)
            cvt8(src + 2 * i, dst + i);
        publish(&g_w1rdy[u]);
        return;
    }
    const int o = id - PREP;
    if (o < MIXLEN && (o & 3) == 3) {
        const int u = o >> 2;
        const long long base8 = ((long long)(u >> 4) * kD + (long long)(u & 15) * 128) * kF / 8;
        uint4* dst = (uint4*)g_w2h + base8;
        const float4* src = w2src + 2 * base8;
#pragma unroll 4
        for (int i = tid; i < W2_UNIT_N8; i += NTH)
            cvt8(src + 2 * i, dst + i);
        publish(&g_w2rdy[u]);
        return;
    }
    if (id < G1END) {
        const int g1 = (o < MIXLEN) ? (o - ((o + 1) >> 2)) : (o - NW2);
        const int rt = g1 >> 5, xblk = g1 & 31;
        const int e = g_tile_expert[rt];
        if (e >= 0) {
            if (tid == 0) {
                while (!ld_acquire(&g_xrdy[rt])) __nanosleep(128);
                while (!ld_acquire(&g_w1rdy[e * XT1 + xblk])) __nanosleep(128);
            }
            __syncthreads();
            gemm_tile<true>(rt, e, xblk, sb, out);
        }
        __threadfence();
        __syncthreads();
        if (tid == 0) atomicAdd(&g_done1[rt], 1);
    } else {
        const int g2 = id - G1END;
        const int rt = g2 >> 4, xblk = g2 & 15;
        const int e = g_tile_expert[rt];
        if (e < 0) return;
        if (tid == 0) {
            while (!ld_acquire(&g_w2rdy[e * XT2 + xblk])) __nanosleep(128);
            while (ld_acquire(&g_done1[rt]) < XT1) __nanosleep(128);
        }
        __syncthreads();
        gemm_tile<false>(rt, e, xblk, sb, out);
    }
}

extern "C" void kernel_launch(void* const* d_in, const int* in_sizes, int n_in,
                              void* d_out, int out_size) {
    const float* hs     = (const float*)d_in[0];
    const float* logits = (const float*)d_in[1];
    const float* w1     = (const float*)d_in[2];
    const float* w2     = (const float*)d_in[3];
    float* out = (float*)d_out;

    cudaFuncSetAttribute(k_moe, cudaFuncAttributeMaxDynamicSharedMemorySize, SMEM_BYTES);

    k_route<<<kT / 256, 256>>>(logits);
    k_offsets<<<1, 256>>>();
    k_scatter<<<kT / 256, 256>>>();
    k_moe<<<TOTAL, NTH, SMEM_BYTES>>>((const float4*)w1, (const float4*)w2,
                                      (const float4*)hs, out);
}

// round 14
// speedup vs baseline: 1.1037x; 1.1037x over previous
#include <cuda_runtime.h>
#include <cuda_fp16.h>
#include <cstdint>
#include <cstddef>

namespace {
constexpr int kT = 8192, kD = 2048, kF = 4096, kE = 8;
constexpr int TMm = 128;
constexpr int TN  = 128;
constexpr int ROWT = kT / TMm + kE;      // 72
constexpr int TPAD = ROWT * TMm;
constexpr int BK = 64;
constexpr int ST = 3;
constexpr int A_BYTES = TMm * BK * 2;    // 16 KB
constexpr int B_BYTES = TN * BK * 2;     // 16 KB
constexpr int STG = A_BYTES + B_BYTES;   // 32 KB
constexpr int SMEM_BYTES = ST * STG;     // 96 KB -> 2 CTAs/SM
constexpr int NTH = 128;                 // 4 warps, warp tile 64x64

constexpr long long W1_N8 = ((long long)kE * kF * kD) / 8;

// moe schedule: pairs of tiles per CTA
constexpr int XT1 = kF / TN;             // 32
constexpr int XT2 = kD / TN;             // 16
constexpr int P1 = XT1 / 2;              // 16 pairs per rt (GEMM1)
constexpr int P2 = XT2 / 2;              // 8 pairs per rt (GEMM2)
constexpr int NT1P = P1 * ROWT;          // 1152
constexpr int NT2P = P2 * ROWT;          // 576
constexpr int NW2 = kE * XT2;            // 128 w2 panel units
constexpr int MIX = 3 * NW2;             // 384: 1-in-3 ids are w2 units
constexpr int PH1 = MIX + (NT1P - 2 * NW2);  // 384 + 896 = 1280
constexpr int TOTAL = PH1 + NT2P;        // 1856
constexpr int W2_UNIT_N8 = 128 * kF / 8; // 65536 uint4 per panel
}

__device__ int g_cursor[kE];
__device__ int g_rowtoken[TPAD];
__device__ int g_tile_expert[ROWT];
__device__ int g_w2rdy[NW2];
__device__ int g_done1[ROWT];
__device__ __half g_xperm[(size_t)TPAD * kD];
__device__ __half g_w1h[(size_t)kE * kF * kD];
__device__ __half g_w2h[(size_t)kE * kD * kF];
__device__ __half g_h1h[(size_t)TPAD * kF];

__device__ __forceinline__ uint32_t smem_u32(const void* p) {
    uint32_t a;
    asm("{ .reg .u64 t; cvta.to.shared.u64 t, %1; cvt.u32.u64 %0, t; }" : "=r"(a) : "l"(p));
    return a;
}
__device__ __forceinline__ void ldsm_x4(uint32_t* r, uint32_t addr) {
    asm volatile("ldmatrix.sync.aligned.m8n8.x4.shared.b16 {%0,%1,%2,%3}, [%4];"
                 : "=r"(r[0]), "=r"(r[1]), "=r"(r[2]), "=r"(r[3]) : "r"(addr));
}
__device__ __forceinline__ void mma_f16(float* c, const uint32_t* a, uint32_t b0, uint32_t b1) {
    asm volatile(
        "mma.sync.aligned.m16n8k16.row.col.f32.f16.f16.f32 "
        "{%0,%1,%2,%3}, {%4,%5,%6,%7}, {%8,%9}, {%0,%1,%2,%3};\n"
        : "+f"(c[0]), "+f"(c[1]), "+f"(c[2]), "+f"(c[3])
        : "r"(a[0]), "r"(a[1]), "r"(a[2]), "r"(a[3]), "r"(b0), "r"(b1));
}
__device__ __forceinline__ void cp_async16(uint32_t dst, const void* src) {
    asm volatile("cp.async.cg.shared.global [%0], [%1], 16;" :: "r"(dst), "l"(src));
}
__device__ __forceinline__ void cvt8(const float4* __restrict__ s, uint4* __restrict__ d) {
    float4 a = s[0], b = s[1];
    __half2 h0 = __floats2half2_rn(a.x, a.y), h1 = __floats2half2_rn(a.z, a.w);
    __half2 h2 = __floats2half2_rn(b.x, b.y), h3 = __floats2half2_rn(b.z, b.w);
    uint4 o;
    o.x = *(uint32_t*)&h0; o.y = *(uint32_t*)&h1;
    o.z = *(uint32_t*)&h2; o.w = *(uint32_t*)&h3;
    *d = o;
}
__device__ __forceinline__ int ld_acquire(const int* p) {
    int v;
    asm volatile("ld.acquire.gpu.global.b32 %0, [%1];" : "=r"(v) : "l"(p) : "memory");
    return v;
}

// ---------------- routing ----------------
__global__ void k_route(const float* __restrict__ logits) {
    int t = blockIdx.x * blockDim.x + threadIdx.x;
    if (t >= kT) return;
    const float* l = logits + (size_t)t * kE;
    int best = 0; float bv = l[0];
#pragma unroll
    for (int e = 1; e < kE; e++) { float v = l[e]; if (v > bv) { bv = v; best = e; } }
    ((int*)g_xperm)[t] = best;
}
__global__ void k_offsets() {
    __shared__ int sc[kE];
    if (threadIdx.x < kE) sc[threadIdx.x] = 0;
    __syncthreads();
    for (int t = threadIdx.x; t < kT; t += blockDim.x)
        atomicAdd(&sc[((int*)g_xperm)[t]], 1);
    __syncthreads();
    if (threadIdx.x == 0) {
        int off = 0;
        for (int e = 0; e < kE; e++) {
            g_cursor[e] = off;
            int nt = (sc[e] + TMm - 1) / TMm;
            for (int i = 0; i < nt; i++) g_tile_expert[off / TMm + i] = e;
            off += nt * TMm;
        }
        for (int rt = off / TMm; rt < ROWT; rt++) g_tile_expert[rt] = -1;
    }
    for (int i = threadIdx.x; i < TPAD; i += blockDim.x) g_rowtoken[i] = -1;
    for (int i = threadIdx.x; i < ROWT; i += blockDim.x) g_done1[i] = 0;
    for (int i = threadIdx.x; i < NW2; i += blockDim.x) g_w2rdy[i] = 0;
}
__global__ void k_scatter() {
    int t = blockIdx.x * blockDim.x + threadIdx.x;
    if (t >= kT) return;
    int e = ((int*)g_xperm)[t];
    int pos = atomicAdd(&g_cursor[e], 1);
    g_rowtoken[pos] = t;
}
// w1 fp32->fp16 + token gather/convert/zero-pad (one DRAM-roofline pass)
__global__ void k_prep(const float4* __restrict__ w1, const float4* __restrict__ hs) {
    long long i = (long long)blockIdx.x * blockDim.x + threadIdx.x;
    if (i < W1_N8) cvt8(w1 + 2 * (size_t)i, ((uint4*)g_w1h) + i);
    if (i < (long long)TPAD * 256) {
        int row = (int)(i >> 8);
        int q = (int)(i & 255);
        int tok = g_rowtoken[row];
        uint4 o = make_uint4(0, 0, 0, 0);
        if (tok >= 0) cvt8(hs + (size_t)tok * (kD / 4) + 2 * q, &o);
        ((uint4*)g_xperm)[i] = o;
    }
}

// ---------------- GEMM pair body -------------------------------------------
// Processes TWO adjacent column tiles (same rt) with one continuous cp.async
// pipeline: tile 2's prefetch is in flight during tile 1's epilogue, hiding
// prologue + epilogue tensor-idle. CTA tile 128x128, 4 warps, 64x64 each.
template <bool FIRST>
__device__ __forceinline__ void gemm_pair(int rt, int e, int xblk0, uint32_t sb,
                                          float* __restrict__ out)
{
    constexpr int K = FIRST ? kD : kF;
    constexpr int NC = K / BK;
    constexpr int TC = 2 * NC;
    const int rowbase = rt * TMm;
    const int colbase0 = xblk0 * TN;

    const int tid = threadIdx.x;
    const int warp = tid >> 5, lane = tid & 31;
    const int wm = warp & 1, wn = warp >> 1;

    const __half* Abase = FIRST ? g_xperm : g_h1h;
    const __half* Wb = (FIRST ? g_w1h : g_w2h) + (size_t)e * ((size_t)(FIRST ? kF : kD) * K);

    const int q = tid & 7, r = tid >> 3;
    const __half* aptr = Abase + (size_t)(rowbase + r) * K + q * 8;
    const __half* bptr0 = Wb + (size_t)(colbase0 + r) * K + q * 8;
    const uint32_t dA = (uint32_t)(r * 128 + ((q ^ (r & 7)) << 4));

    auto prefetch = [&](int i) {           // i = global chunk index 0..TC-1
        const int tile = i >= NC;
        const int c = i - (tile ? NC : 0);
        const uint32_t base = sb + (uint32_t)((i % ST) * STG);
        const __half* ap = aptr + c * BK;
#pragma unroll
        for (int p = 0; p < 8; p++)
            cp_async16(base + dA + (uint32_t)(p * 16 * 128), ap + (size_t)p * 16 * K);
        const __half* bp = bptr0 + (size_t)tile * TN * K + c * BK;
#pragma unroll
        for (int p = 0; p < 8; p++)
            cp_async16(base + A_BYTES + dA + (uint32_t)(p * 16 * 128), bp + (size_t)p * 16 * K);
        asm volatile("cp.async.commit_group;" ::: "memory");
    };

    prefetch(0);
    prefetch(1);

    const int rowA = wm * 64 + (lane & 15);
    const int kgA = lane >> 4;
    const int rowB = wn * 64 + ((lane >> 4) << 3) + (lane & 7);
    const int kgB = (lane >> 3) & 1;
    const int g = lane >> 2, tig = lane & 3;

    float acc[4][8][4];
#pragma unroll
    for (int i = 0; i < 4; i++)
#pragma unroll
        for (int j = 0; j < 8; j++)
#pragma unroll
            for (int v = 0; v < 4; v++) acc[i][j][v] = 0.f;

    auto epilogue = [&](int colbase) {
#pragma unroll
        for (int mi = 0; mi < 4; mi++) {
#pragma unroll
            for (int rr = 0; rr < 2; rr++) {
                const int lrow = rowbase + wm * 64 + mi * 16 + g + rr * 8;
                if (FIRST) {
                    __half* hp = g_h1h + (size_t)lrow * kF + colbase;
#pragma unroll
                    for (int nj = 0; nj < 8; nj++) {
                        const int col = wn * 64 + nj * 8 + tig * 2;
                        float v0 = acc[mi][nj][rr * 2 + 0];
                        float v1 = acc[mi][nj][rr * 2 + 1];
                        v0 = v0 / (1.f + __expf(-v0));       // SiLU
                        v1 = v1 / (1.f + __expf(-v1));
                        __half2 h = __floats2half2_rn(v0, v1);
                        *(uint32_t*)(hp + col) = *(uint32_t*)&h;
                    }
                } else {
                    const int tok = g_rowtoken[lrow];
                    if (tok >= 0) {
                        float* op = out + (size_t)tok * kD + colbase;
#pragma unroll
                        for (int nj = 0; nj < 8; nj++) {
                            const int col = wn * 64 + nj * 8 + tig * 2;
                            float2 st;
                            st.x = acc[mi][nj][rr * 2 + 0];
                            st.y = acc[mi][nj][rr * 2 + 1];
                            *(float2*)(op + col) = st;
                        }
                    }
                }
                // reset acc for next tile
#pragma unroll
                for (int nj = 0; nj < 8; nj++) {
                    acc[mi][nj][rr * 2 + 0] = 0.f;
                    acc[mi][nj][rr * 2 + 1] = 0.f;
                }
            }
        }
    };

#pragma unroll 1
    for (int i = 0; i < TC; i++) {
        if (i < TC - 1) asm volatile("cp.async.wait_group 1;" ::: "memory");
        else            asm volatile("cp.async.wait_group 0;" ::: "memory");
        __syncthreads();
        if (i + 2 < TC) prefetch(i + 2);

        const uint32_t stA = sb + (uint32_t)((i % ST) * STG);
        const uint32_t stB = stA + A_BYTES;
#pragma unroll
        for (int s = 0; s < 4; s++) {
            uint32_t a[4][4];
#pragma unroll
            for (int mi = 0; mi < 4; mi++) {
                const int rr = rowA + mi * 16;
                ldsm_x4(a[mi], stA + (uint32_t)(rr * 128 + (((2 * s + kgA) ^ (rr & 7)) << 4)));
            }
            uint32_t b[4][4];
#pragma unroll
            for (int nj2 = 0; nj2 < 4; nj2++) {
                const int rr = rowB + nj2 * 16;
                ldsm_x4(b[nj2], stB + (uint32_t)(rr * 128 + (((2 * s + kgB) ^ (rr & 7)) << 4)));
            }
#pragma unroll
            for (int mi = 0; mi < 4; mi++)
#pragma unroll
                for (int nj = 0; nj < 8; nj++)
                    mma_f16(acc[mi][nj], a[mi], b[nj >> 1][(nj & 1) * 2], b[nj >> 1][(nj & 1) * 2 + 1]);
        }
        if (i == NC - 1) epilogue(colbase0);      // tile-2 prefetches in flight
    }
    epilogue(colbase0 + TN);
}

// ---------------- fused [w2cvt || GEMM1-pairs] then GEMM2-pairs ------------
// ids: [0,384): id%3==2 -> w2 panel unit id/3; else GEMM1 pair id-(id+1)/3
//      [384,1280): GEMM1 pair id-128
//      [1280,1856): GEMM2 pair (spins on its 2 w2 panels + done1[rt]==16)
__global__ __launch_bounds__(NTH, 2) void k_moe(const float4* __restrict__ w2src,
                                                float* __restrict__ out)
{
    extern __shared__ char smem[];
    const uint32_t sb = smem_u32(smem);
    const int tid = threadIdx.x;
    const int id = blockIdx.x;

    if (id < PH1) {
        if (id < MIX && (id % 3) == 2) {
            // ---- w2 panel (e, xblk) fp32->fp16 ----
            const int u = id / 3;
            const long long base8 = ((long long)(u >> 4) * kD + (long long)(u & 15) * 128) * kF / 8;
            uint4* dst = (uint4*)g_w2h + base8;
            const float4* src = w2src + 2 * base8;
#pragma unroll 4
            for (int i = tid; i < W2_UNIT_N8; i += NTH)
                cvt8(src + 2 * i, dst + i);
            __threadfence();
            __syncthreads();
            if (tid == 0) atomicExch(&g_w2rdy[u], 1);
            return;
        }
        const int g1 = (id < MIX) ? (id - (id + 1) / 3) : (id - NW2);
        const int rt = g1 >> 4, pr = g1 & 15;             // 16 pairs per rt
        const int e = g_tile_expert[rt];
        if (e >= 0) gemm_pair<true>(rt, e, pr * 2, sb, out);
        __threadfence();
        __syncthreads();
        if (tid == 0) atomicAdd(&g_done1[rt], 1);
    } else {
        const int g2 = id - PH1;
        const int rt = g2 >> 3, pr = g2 & 7;              // 8 pairs per rt
        const int e = g_tile_expert[rt];
        if (e < 0) return;
        const int u0 = e * XT2 + pr * 2;
        if (tid == 0) {
            while (!ld_acquire(&g_w2rdy[u0]))     __nanosleep(128);
            while (!ld_acquire(&g_w2rdy[u0 + 1])) __nanosleep(128);
            while (ld_acquire(&g_done1[rt]) < P1) __nanosleep(128);
        }
        __syncthreads();
        gemm_pair<false>(rt, e, pr * 2, sb, out);
    }
}

// ---------------- entry ----------------
extern "C" void kernel_launch(void* const* d_in, const int* in_sizes, int n_in,
                              void* d_out, int out_size) {
    const float* hs     = (const float*)d_in[0];
    const float* logits = (const float*)d_in[1];
    const float* w1     = (const float*)d_in[2];
    const float* w2     = (const float*)d_in[3];
    float* out = (float*)d_out;

    cudaFuncSetAttribute(k_moe, cudaFuncAttributeMaxDynamicSharedMemorySize, SMEM_BYTES);

    k_route<<<kT / 256, 256>>>(logits);
    k_offsets<<<1, 256>>>();
    k_scatter<<<kT / 256, 256>>>();
    k_prep<<<(unsigned)((W1_N8 + 255) / 256), 256>>>((const float4*)w1, (const float4*)hs);

    k_moe<<<TOTAL, NTH, SMEM_BYTES>>>((const float4*)w2, out);
}

// round 15
// speedup vs baseline: 1.1411x; 1.0339x over previous
#include <cuda_runtime.h>
#include <cuda_fp16.h>
#include <cstdint>
#include <cstddef>

namespace {
constexpr int kT = 8192, kD = 2048, kF = 4096, kE = 8;
constexpr int TMm = 128;
constexpr int TN  = 128;
constexpr int ROWT = kT / TMm + kE;      // 72
constexpr int TPAD = ROWT * TMm;
constexpr int BK = 64;
constexpr int ST = 3;
constexpr int A_BYTES = TMm * BK * 2;    // 16 KB
constexpr int B_BYTES = TN * BK * 2;     // 16 KB
constexpr int STG = A_BYTES + B_BYTES;   // 32 KB
constexpr int SMEM_BYTES = ST * STG;     // 96 KB -> 2 CTAs/SM
constexpr int NTH = 128;                 // 4 warps, warp tile 64x64

constexpr long long W1_N8 = ((long long)kE * kF * kD) / 8;

// fused schedule (R12 shape): [w2cvt || GEMM1] then GEMM2
constexpr int XT1 = kF / TN;             // 32
constexpr int XT2 = kD / TN;             // 16
constexpr int NT1 = XT1 * ROWT;          // 2304
constexpr int NT2 = XT2 * ROWT;          // 1152
constexpr int NW2 = kE * XT2;            // 128 w2 panel units
constexpr int NCVT = 512;                // w2-cvt slices: 4 per panel
constexpr int SL_PER_PANEL = NCVT / NW2; // 4
constexpr int MIX = 3 * NCVT;            // 1536
constexpr int PH1 = NT1 + NCVT;          // 2816
constexpr int TOTAL = PH1 + NT2;         // 3968
constexpr long long W2_N8 = ((long long)kE * kD * kF) / 8;
constexpr int CVT_CHUNK = (int)(W2_N8 / NCVT);   // 16384 uint4 per slice
}

__device__ int g_cursor[kE];
__device__ int g_rowtoken[TPAD];
__device__ int g_tile_expert[ROWT];
__device__ int g_w2rdy[NW2];             // per-panel slice counters (4 => ready)
__device__ int g_done1[ROWT];
__device__ __half g_xperm[(size_t)TPAD * kD];
__device__ __half g_w1h[(size_t)kE * kF * kD];
__device__ __half g_w2h[(size_t)kE * kD * kF];
__device__ __half g_h1h[(size_t)TPAD * kF];

__device__ __forceinline__ uint32_t smem_u32(const void* p) {
    uint32_t a;
    asm("{ .reg .u64 t; cvta.to.shared.u64 t, %1; cvt.u32.u64 %0, t; }" : "=r"(a) : "l"(p));
    return a;
}
__device__ __forceinline__ void ldsm_x4(uint32_t* r, uint32_t addr) {
    asm volatile("ldmatrix.sync.aligned.m8n8.x4.shared.b16 {%0,%1,%2,%3}, [%4];"
                 : "=r"(r[0]), "=r"(r[1]), "=r"(r[2]), "=r"(r[3]) : "r"(addr));
}
__device__ __forceinline__ void mma_f16(float* c, const uint32_t* a, uint32_t b0, uint32_t b1) {
    asm volatile(
        "mma.sync.aligned.m16n8k16.row.col.f32.f16.f16.f32 "
        "{%0,%1,%2,%3}, {%4,%5,%6,%7}, {%8,%9}, {%0,%1,%2,%3};\n"
        : "+f"(c[0]), "+f"(c[1]), "+f"(c[2]), "+f"(c[3])
        : "r"(a[0]), "r"(a[1]), "r"(a[2]), "r"(a[3]), "r"(b0), "r"(b1));
}
__device__ __forceinline__ void cp_async16(uint32_t dst, const void* src) {
    asm volatile("cp.async.cg.shared.global [%0], [%1], 16;" :: "r"(dst), "l"(src));
}
__device__ __forceinline__ void cvt8(const float4* __restrict__ s, uint4* __restrict__ d) {
    float4 a = s[0], b = s[1];
    __half2 h0 = __floats2half2_rn(a.x, a.y), h1 = __floats2half2_rn(a.z, a.w);
    __half2 h2 = __floats2half2_rn(b.x, b.y), h3 = __floats2half2_rn(b.z, b.w);
    uint4 o;
    o.x = *(uint32_t*)&h0; o.y = *(uint32_t*)&h1;
    o.z = *(uint32_t*)&h2; o.w = *(uint32_t*)&h3;
    *d = o;
}
__device__ __forceinline__ int ld_acquire(const int* p) {
    int v;
    asm volatile("ld.acquire.gpu.global.b32 %0, [%1];" : "=r"(v) : "l"(p) : "memory");
    return v;
}
// fast SiLU: MUFU.EX2 + MUFU.RCP + FMUL (no refined division)
__device__ __forceinline__ float fast_silu(float v) {
    return __fdividef(v, 1.f + __expf(-v));
}

// ---------------- routing ----------------
__global__ void k_route(const float* __restrict__ logits) {
    int t = blockIdx.x * blockDim.x + threadIdx.x;
    if (t >= kT) return;
    const float* l = logits + (size_t)t * kE;
    int best = 0; float bv = l[0];
#pragma unroll
    for (int e = 1; e < kE; e++) { float v = l[e]; if (v > bv) { bv = v; best = e; } }
    ((int*)g_xperm)[t] = best;
}
__global__ void k_offsets() {
    __shared__ int sc[kE];
    if (threadIdx.x < kE) sc[threadIdx.x] = 0;
    __syncthreads();
    for (int t = threadIdx.x; t < kT; t += blockDim.x)
        atomicAdd(&sc[((int*)g_xperm)[t]], 1);
    __syncthreads();
    if (threadIdx.x == 0) {
        int off = 0;
        for (int e = 0; e < kE; e++) {
            g_cursor[e] = off;
            int nt = (sc[e] + TMm - 1) / TMm;
            for (int i = 0; i < nt; i++) g_tile_expert[off / TMm + i] = e;
            off += nt * TMm;
        }
        for (int rt = off / TMm; rt < ROWT; rt++) g_tile_expert[rt] = -1;
    }
    for (int i = threadIdx.x; i < TPAD; i += blockDim.x) g_rowtoken[i] = -1;
    for (int i = threadIdx.x; i < ROWT; i += blockDim.x) g_done1[i] = 0;
    for (int i = threadIdx.x; i < NW2; i += blockDim.x) g_w2rdy[i] = 0;
}
__global__ void k_scatter() {
    int t = blockIdx.x * blockDim.x + threadIdx.x;
    if (t >= kT) return;
    int e = ((int*)g_xperm)[t];
    int pos = atomicAdd(&g_cursor[e], 1);
    g_rowtoken[pos] = t;
}
// w1 fp32->fp16 + token gather/convert/zero-pad (DRAM-roofline pass)
__global__ void k_prep(const float4* __restrict__ w1, const float4* __restrict__ hs) {
    long long i = (long long)blockIdx.x * blockDim.x + threadIdx.x;
    if (i < W1_N8) cvt8(w1 + 2 * (size_t)i, ((uint4*)g_w1h) + i);
    if (i < (long long)TPAD * 256) {
        int row = (int)(i >> 8);
        int q = (int)(i & 255);
        int tok = g_rowtoken[row];
        uint4 o = make_uint4(0, 0, 0, 0);
        if (tok >= 0) cvt8(hs + (size_t)tok * (kD / 4) + 2 * q, &o);
        ((uint4*)g_xperm)[i] = o;
    }
}

// ---------------- GEMM tile body (proven R12 mainloop) ---------------------
template <bool FIRST>
__device__ __forceinline__ void gemm_tile(int rt, int e, int xblk, uint32_t sb,
                                          float* __restrict__ out)
{
    constexpr int K = FIRST ? kD : kF;
    constexpr int NC = K / BK;
    const int rowbase = rt * TMm;
    const int colbase = xblk * TN;

    const int tid = threadIdx.x;
    const int warp = tid >> 5, lane = tid & 31;
    const int wm = warp & 1, wn = warp >> 1;

    const __half* Abase = FIRST ? g_xperm : g_h1h;
    const __half* Wb = (FIRST ? g_w1h : g_w2h) + (size_t)e * ((size_t)(FIRST ? kF : kD) * K);

    const int q = tid & 7, r = tid >> 3;
    const __half* aptr = Abase + (size_t)(rowbase + r) * K + q * 8;
    const __half* bptr = Wb + (size_t)(colbase + r) * K + q * 8;
    const uint32_t dA = (uint32_t)(r * 128 + ((q ^ (r & 7)) << 4));

    auto prefetch = [&](int c) {
        const uint32_t base = sb + (uint32_t)((c % ST) * STG);
        const __half* ap = aptr + c * BK;
#pragma unroll
        for (int p = 0; p < 8; p++)
            cp_async16(base + dA + (uint32_t)(p * 16 * 128), ap + (size_t)p * 16 * K);
        const __half* bp = bptr + c * BK;
#pragma unroll
        for (int p = 0; p < 8; p++)
            cp_async16(base + A_BYTES + dA + (uint32_t)(p * 16 * 128), bp + (size_t)p * 16 * K);
        asm volatile("cp.async.commit_group;" ::: "memory");
    };

    prefetch(0);
    prefetch(1);

    const int rowA = wm * 64 + (lane & 15);
    const int kgA = lane >> 4;
    const int rowB = wn * 64 + ((lane >> 4) << 3) + (lane & 7);
    const int kgB = (lane >> 3) & 1;

    float acc[4][8][4];
#pragma unroll
    for (int i = 0; i < 4; i++)
#pragma unroll
        for (int j = 0; j < 8; j++)
#pragma unroll
            for (int v = 0; v < 4; v++) acc[i][j][v] = 0.f;

#pragma unroll 1
    for (int c = 0; c < NC; c++) {
        if (c < NC - 1) asm volatile("cp.async.wait_group 1;" ::: "memory");
        else            asm volatile("cp.async.wait_group 0;" ::: "memory");
        __syncthreads();
        if (c + 2 < NC) prefetch(c + 2);

        const uint32_t stA = sb + (uint32_t)((c % ST) * STG);
        const uint32_t stB = stA + A_BYTES;
#pragma unroll
        for (int s = 0; s < 4; s++) {
            uint32_t a[4][4];
#pragma unroll
            for (int mi = 0; mi < 4; mi++) {
                const int rr = rowA + mi * 16;
                ldsm_x4(a[mi], stA + (uint32_t)(rr * 128 + (((2 * s + kgA) ^ (rr & 7)) << 4)));
            }
            uint32_t b[4][4];
#pragma unroll
            for (int nj2 = 0; nj2 < 4; nj2++) {
                const int rr = rowB + nj2 * 16;
                ldsm_x4(b[nj2], stB + (uint32_t)(rr * 128 + (((2 * s + kgB) ^ (rr & 7)) << 4)));
            }
#pragma unroll
            for (int mi = 0; mi < 4; mi++)
#pragma unroll
                for (int nj = 0; nj < 8; nj++)
                    mma_f16(acc[mi][nj], a[mi], b[nj >> 1][(nj & 1) * 2], b[nj >> 1][(nj & 1) * 2 + 1]);
        }
    }

    const int g = lane >> 2, tig = lane & 3;
#pragma unroll
    for (int mi = 0; mi < 4; mi++) {
#pragma unroll
        for (int rr = 0; rr < 2; rr++) {
            const int lrow = rowbase + wm * 64 + mi * 16 + g + rr * 8;
            if (FIRST) {
                __half* hp = g_h1h + (size_t)lrow * kF + colbase;
#pragma unroll
                for (int nj = 0; nj < 8; nj++) {
                    const int col = wn * 64 + nj * 8 + tig * 2;
                    __half2 h = __floats2half2_rn(fast_silu(acc[mi][nj][rr * 2 + 0]),
                                                  fast_silu(acc[mi][nj][rr * 2 + 1]));
                    *(uint32_t*)(hp + col) = *(uint32_t*)&h;
                }
            } else {
                const int tok = g_rowtoken[lrow];
                if (tok >= 0) {
                    float* op = out + (size_t)tok * kD + colbase;
#pragma unroll
                    for (int nj = 0; nj < 8; nj++) {
                        const int col = wn * 64 + nj * 8 + tig * 2;
                        float2 st;
                        st.x = acc[mi][nj][rr * 2 + 0];
                        st.y = acc[mi][nj][rr * 2 + 1];
                        *(float2*)(op + col) = st;
                    }
                }
            }
        }
    }
}

// ---------------- fused launch: [w2cvt || GEMM1] then GEMM2 ----------------
// ids: [0,1536): id%3==2 -> cvt slice id/3 (panel u = slice/4), else GEMM1
//      [1536,2816): GEMM1 tile id-512
//      [2816,3968): GEMM2 tile (spins on its w2 panel + done1[rt]==32)
__global__ __launch_bounds__(NTH, 2) void k_moe(const float4* __restrict__ w2src,
                                                float* __restrict__ out)
{
    extern __shared__ char smem[];
    const uint32_t sb = smem_u32(smem);
    const int tid = threadIdx.x;
    const int id = blockIdx.x;

    if (id < PH1) {
        if (id < MIX && (id % 3) == 2) {
            // ---- w2 fp32->fp16 slice (1/4 of a panel) ----
            const int slice = id / 3;
            const long long base = (long long)slice * CVT_CHUNK;
            uint4* dst = (uint4*)g_w2h;
#pragma unroll 4
            for (int i = tid; i < CVT_CHUNK; i += NTH)
                cvt8(w2src + 2 * (size_t)(base + i), dst + base + i);
            __threadfence();
            __syncthreads();
            if (tid == 0) atomicAdd(&g_w2rdy[slice / SL_PER_PANEL], 1);
            return;
        }
        const int g1 = (id < MIX) ? (id - (id + 1) / 3) : (id - NCVT);
        const int rt = g1 >> 5, xblk = g1 & 31;
        const int e = g_tile_expert[rt];
        if (e >= 0) gemm_tile<true>(rt, e, xblk, sb, out);
        __threadfence();
        __syncthreads();
        if (tid == 0) atomicAdd(&g_done1[rt], 1);
    } else {
        const int g2 = id - PH1;
        const int rt = g2 >> 4, xblk = g2 & 15;
        const int e = g_tile_expert[rt];
        if (e < 0) return;
        if (tid == 0) {
            // wait only this tile's w2 panel (4 slices) + all GEMM1 tiles of rt
            while (ld_acquire(&g_w2rdy[e * XT2 + xblk]) < SL_PER_PANEL) __nanosleep(128);
            while (ld_acquire(&g_done1[rt]) < XT1) __nanosleep(128);
        }
        __syncthreads();
        gemm_tile<false>(rt, e, xblk, sb, out);
    }
}

// ---------------- entry ----------------
extern "C" void kernel_launch(void* const* d_in, const int* in_sizes, int n_in,
                              void* d_out, int out_size) {
    const float* hs     = (const float*)d_in[0];
    const float* logits = (const float*)d_in[1];
    const float* w1     = (const float*)d_in[2];
    const float* w2     = (const float*)d_in[3];
    float* out = (float*)d_out;

    cudaFuncSetAttribute(k_moe, cudaFuncAttributeMaxDynamicSharedMemorySize, SMEM_BYTES);

    k_route<<<kT / 256, 256>>>(logits);
    k_offsets<<<1, 256>>>();
    k_scatter<<<kT / 256, 256>>>();
    k_prep<<<(unsigned)((W1_N8 + 255) / 256), 256>>>((const float4*)w1, (const float4*)hs);

    k_moe<<<TOTAL, NTH, SMEM_BYTES>>>((const float4*)w2, out);
}